// round 7
// baseline (speedup 1.0000x reference)
#include <cuda_runtime.h>
#include <cuda_bf16.h>
#include <stdint.h>

#define NN 50000
#define EE 400000
#define IN_DIM 256
#define H1 512
#define H2 128

// ---------------- scratch (device globals; device-side references only) -----
__device__ int   g_is64;                    // edge_index dtype flag
__device__ int   g_mask_kind;               // 0=u8, 1=f32, 2=i32, 3=i64
__device__ int   g_src[EE];                 // int32 src indices
__device__ int   g_dst[EE];                 // int32 dst indices
__device__ float g_norm[EE];                // dis[src]*dis[dst] per edge
__device__ float g_dis[NN];                 // deg -> rsqrt(deg) in place
__device__ float g_h1[(size_t)NN * H1];     // x @ W1
__device__ float g_agg1[(size_t)NN * H1];   // aggregated; then feat1 in place
__device__ float g_h2[(size_t)NN * H2];     // feat1 @ W2
__device__ float g_agg2[(size_t)NN * H2];   // aggregated layer 2

// ---------------- dtype detection ----------------
__global__ void detect_dtype_k(const void* ei_raw, const void* mask_raw) {
    // edge_index: int64 entries lie in [0, NN); int32 data misread as int64
    // gives lo + hi*2^32 with hi a node index (nonzero for ~all entries).
    const long long* e64 = (const long long*)ei_raw;
    int ok64 = 1;
    for (int i = 0; i < 256; i++) {
        long long v = e64[i];
        if (v < 0 || v >= NN) { ok64 = 0; break; }
    }
    g_is64 = ok64;

    // mask dtype, 4-way:
    //   float32 words: {0x00000000, 0x3F800000}
    //   int32 words:   {0, 1}
    //   int64 words:   {0, 1} with every odd word == 0
    //   uint8 bytes:   words are packed 0/1 bytes (e.g. 0x00010100)
    const unsigned* mw = (const unsigned*)mask_raw;
    int all_f32 = 1, all_01 = 1, odd_zero = 1;
    for (int i = 0; i < 256; i++) {
        unsigned v = mw[i];
        if (v != 0u && v != 0x3F800000u) all_f32 = 0;
        if (v > 1u) all_01 = 0;
        if ((i & 1) && v != 0u) odd_zero = 0;
    }
    if (all_f32)            g_mask_kind = 1;
    else if (all_01 && odd_zero) g_mask_kind = 3;
    else if (all_01)        g_mask_kind = 2;
    else                    g_mask_kind = 0;
}

__global__ void convert_edges_k(const void* ei_raw) {
    int e = blockIdx.x * blockDim.x + threadIdx.x;
    if (e >= EE) return;
    if (g_is64) {
        const long long* e64 = (const long long*)ei_raw;
        g_src[e] = (int)e64[e];
        g_dst[e] = (int)e64[EE + e];
    } else {
        const int* e32 = (const int*)ei_raw;
        g_src[e] = e32[e];
        g_dst[e] = e32[EE + e];
    }
}

// ---------------- degree / normalization ----------------
__global__ void init_deg_k() {
    int i = blockIdx.x * blockDim.x + threadIdx.x;
    if (i < NN) g_dis[i] = 1.0f;  // self-loop contributes 1
}

__global__ void deg_accum_k() {
    int e = blockIdx.x * blockDim.x + threadIdx.x;
    if (e < EE) atomicAdd(&g_dis[g_dst[e]], 1.0f);
}

__global__ void finalize_dis_k() {
    int i = blockIdx.x * blockDim.x + threadIdx.x;
    if (i < NN) g_dis[i] = rsqrtf(g_dis[i]);  // deg >= 1 always
}

__global__ void edge_norm_k() {
    int e = blockIdx.x * blockDim.x + threadIdx.x;
    if (e < EE) g_norm[e] = g_dis[g_src[e]] * g_dis[g_dst[e]];
}

// ---------------- zero the aggregation buffers ----------------
template <int LAYER>
__global__ void zero_k() {
    float* p = (LAYER == 1) ? g_agg1 : g_agg2;
    const int n = (LAYER == 1) ? NN * H1 : NN * H2;
    int i = blockIdx.x * blockDim.x + threadIdx.x;
    if (i < n) p[i] = 0.0f;
}

// ---------------- SGEMM: C[M x Nc] = A[M x K] @ B[K x Nc], row-major --------
template <int LAYER>
__global__ void sgemm_k(const float* __restrict__ Ap, const float* __restrict__ B) {
    constexpr int K  = (LAYER == 1) ? IN_DIM : H1;
    constexpr int Nc = (LAYER == 1) ? H1 : H2;
    constexpr int M  = NN;
    const float* __restrict__ A = (LAYER == 1) ? Ap : g_agg1;
    float* __restrict__ C       = (LAYER == 1) ? g_h1 : g_h2;

    const int BM = 64, BN = 64, BK = 16;
    __shared__ float As[BK][BM];
    __shared__ float Bs[BK][BN];

    int tid = threadIdx.x;
    int tx = tid & 15;
    int ty = tid >> 4;
    int block_row = blockIdx.y * BM;
    int block_col = blockIdx.x * BN;

    float acc[4][4];
#pragma unroll
    for (int i = 0; i < 4; i++)
#pragma unroll
        for (int j = 0; j < 4; j++) acc[i][j] = 0.0f;

    for (int k0 = 0; k0 < K; k0 += BK) {
#pragma unroll
        for (int l = 0; l < 4; l++) {
            int idx = tid + l * 256;
            int m = idx >> 4;
            int k = idx & 15;
            int row = block_row + m;
            As[k][m] = (row < M) ? A[(size_t)row * K + k0 + k] : 0.0f;
        }
#pragma unroll
        for (int l = 0; l < 4; l++) {
            int idx = tid + l * 256;
            int k = idx >> 6;
            int n = idx & 63;
            Bs[k][n] = B[(size_t)(k0 + k) * Nc + block_col + n];
        }
        __syncthreads();

#pragma unroll
        for (int kk = 0; kk < BK; kk++) {
            float4 a4 = *reinterpret_cast<const float4*>(&As[kk][ty * 4]);
            float4 b4 = *reinterpret_cast<const float4*>(&Bs[kk][tx * 4]);
            float a[4] = {a4.x, a4.y, a4.z, a4.w};
            float b[4] = {b4.x, b4.y, b4.z, b4.w};
#pragma unroll
            for (int i = 0; i < 4; i++)
#pragma unroll
                for (int j = 0; j < 4; j++) acc[i][j] += a[i] * b[j];
        }
        __syncthreads();
    }

#pragma unroll
    for (int i = 0; i < 4; i++) {
        int row = block_row + ty * 4 + i;
        if (row < M) {
            int col = block_col + tx * 4;
            float4 v = make_float4(acc[i][0], acc[i][1], acc[i][2], acc[i][3]);
            *reinterpret_cast<float4*>(&C[(size_t)row * Nc + col]) = v;
        }
    }
}

// ---------------- edge aggregation: AGG[dst] += H[src] * norm ----------------
template <int LAYER>
__global__ void aggregate_k() {
    constexpr int F = (LAYER == 1) ? H1 : H2;
    const float* __restrict__ H = (LAYER == 1) ? g_h1 : g_h2;
    float* __restrict__ AGG     = (LAYER == 1) ? g_agg1 : g_agg2;

    const int FC = F / 4;
    long long tid = (long long)blockIdx.x * blockDim.x + threadIdx.x;
    if (tid >= (long long)EE * FC) return;
    int e = (int)(tid / FC);
    int f = (int)(tid % FC) * 4;
    int s = g_src[e];
    int d = g_dst[e];
    float nrm = g_norm[e];
    float4 v = *reinterpret_cast<const float4*>(&H[(size_t)s * F + f]);
    float* o = &AGG[(size_t)d * F + f];
    atomicAdd(o + 0, v.x * nrm);
    atomicAdd(o + 1, v.y * nrm);
    atomicAdd(o + 2, v.z * nrm);
    atomicAdd(o + 3, v.w * nrm);
}

// ---------------- epilogue: + self-loop + bias, PReLU, dropout ----------------
template <int LAYER>
__global__ void epilogue_k(const float* __restrict__ bias,
                           const void* __restrict__ mask_raw,
                           const float* __restrict__ a_ptr,
                           float* __restrict__ out_param) {
    constexpr int F = (LAYER == 1) ? H1 : H2;
    const float* __restrict__ Hh  = (LAYER == 1) ? g_h1 : g_h2;
    const float* __restrict__ AGG = (LAYER == 1) ? g_agg1 : g_agg2;
    float* __restrict__ OUT       = (LAYER == 1) ? g_agg1 : out_param;

    int tid = blockIdx.x * blockDim.x + threadIdx.x;
    if (tid >= NN * F) return;
    int i = tid / F;
    int f = tid & (F - 1);
    float dis = g_dis[i];
    float v = AGG[tid] + Hh[tid] * (dis * dis) + bias[f];
    float a = __ldg(a_ptr);
    v = (v >= 0.0f) ? v : a * v;

    bool keep;
    int mk = g_mask_kind;
    if (mk == 1)      keep = ((const float*)mask_raw)[tid] != 0.0f;
    else if (mk == 2) keep = ((const int*)mask_raw)[tid] != 0;
    else if (mk == 3) keep = ((const long long*)mask_raw)[tid] != 0;
    else              keep = ((const unsigned char*)mask_raw)[tid] != 0;

    v = keep ? v * 2.0f : 0.0f;  // scale = 1/(1-0.5)
    OUT[tid] = v;
}

// ---------------- launch: kernel launches ONLY (graph-capturable) ----------
extern "C" void kernel_launch(void* const* d_in, const int* in_sizes, int n_in,
                              void* d_out, int out_size) {
    const float* x      = (const float*)d_in[0];
    const void*  ei_raw = d_in[1];
    const float* W1     = (const float*)d_in[2];
    const float* b1     = (const float*)d_in[3];
    const float* W2     = (const float*)d_in[4];
    const float* b2     = (const float*)d_in[5];
    const float* a      = (const float*)d_in[6];
    const void*  m1     = d_in[7];
    const void*  m2     = d_in[8];
    float* out          = (float*)d_out;

    const int T = 256;

    // dtype detection + edge prep + normalization
    detect_dtype_k<<<1, 1>>>(ei_raw, m1);
    convert_edges_k<<<(EE + T - 1) / T, T>>>(ei_raw);
    init_deg_k<<<(NN + T - 1) / T, T>>>();
    deg_accum_k<<<(EE + T - 1) / T, T>>>();
    finalize_dis_k<<<(NN + T - 1) / T, T>>>();
    edge_norm_k<<<(EE + T - 1) / T, T>>>();

    // ---- layer 1 ----
    zero_k<1><<<(NN * H1 + T - 1) / T, T>>>();
    {
        dim3 grid(H1 / 64, (NN + 63) / 64);
        sgemm_k<1><<<grid, 256>>>(x, W1);
    }
    {
        long long work = (long long)EE * (H1 / 4);
        aggregate_k<1><<<(int)((work + T - 1) / T), T>>>();
    }
    epilogue_k<1><<<(NN * H1 + T - 1) / T, T>>>(b1, m1, a, nullptr);

    // ---- layer 2 ----
    zero_k<2><<<(NN * H2 + T - 1) / T, T>>>();
    {
        dim3 grid(H2 / 64, (NN + 63) / 64);
        sgemm_k<2><<<grid, 256>>>(x /*unused for layer 2*/, W2);
    }
    {
        long long work = (long long)EE * (H2 / 4);
        aggregate_k<2><<<(int)((work + T - 1) / T), T>>>();
    }
    epilogue_k<2><<<(NN * H2 + T - 1) / T, T>>>(b2, m2, a, out);
}

// round 8
// speedup vs baseline: 1.4205x; 1.4205x over previous
#include <cuda_runtime.h>
#include <cuda_bf16.h>
#include <stdint.h>

#define NN 50000
#define EE 400000
#define IN_DIM 256
#define H1 512
#define H2 128

// ---------------- scratch (device globals; device-side references only) -----
__device__ int   g_is64;                     // edge_index dtype flag
__device__ int   g_mask_kind;                // 0=u8, 1=f32, 2=i32, 3=i64
__device__ int   g_src[EE];
__device__ int   g_dst[EE];
__device__ float g_norm[EE];                 // dis[src]*dis[dst]
__device__ float g_dis[NN];                  // rsqrt(deg)
__device__ float g_aggx[(size_t)NN * IN_DIM]; // aggregated x (layer1, pre-GEMM)
__device__ float g_h1[(size_t)NN * H1];       // aggx @ W1
__device__ float g_feat1[(size_t)NN * H1];    // after epilogue1
__device__ float g_h2[(size_t)NN * H2];       // feat1 @ W2
__device__ float g_agg2[(size_t)NN * H2];     // aggregated layer 2

// ---------------- dtype detection ----------------
__global__ void detect_dtype_k(const void* ei_raw, const void* mask_raw) {
    const long long* e64 = (const long long*)ei_raw;
    int ok64 = 1;
    for (int i = 0; i < 256; i++) {
        long long v = e64[i];
        if (v < 0 || v >= NN) { ok64 = 0; break; }
    }
    g_is64 = ok64;

    const unsigned* mw = (const unsigned*)mask_raw;
    int all_f32 = 1, all_01 = 1, odd_zero = 1;
    for (int i = 0; i < 256; i++) {
        unsigned v = mw[i];
        if (v != 0u && v != 0x3F800000u) all_f32 = 0;
        if (v > 1u) all_01 = 0;
        if ((i & 1) && v != 0u) odd_zero = 0;
    }
    if (all_f32)                 g_mask_kind = 1;
    else if (all_01 && odd_zero) g_mask_kind = 3;
    else if (all_01)             g_mask_kind = 2;
    else                         g_mask_kind = 0;
}

__global__ void convert_edges_k(const void* ei_raw) {
    int e = blockIdx.x * blockDim.x + threadIdx.x;
    if (e >= EE) return;
    if (g_is64) {
        const long long* e64 = (const long long*)ei_raw;
        g_src[e] = (int)e64[e];
        g_dst[e] = (int)e64[EE + e];
    } else {
        const int* e32 = (const int*)ei_raw;
        g_src[e] = e32[e];
        g_dst[e] = e32[EE + e];
    }
}

// ---------------- degree / normalization ----------------
__global__ void init_deg_k() {
    int i = blockIdx.x * blockDim.x + threadIdx.x;
    if (i < NN) g_dis[i] = 1.0f;
}
__global__ void deg_accum_k() {
    int e = blockIdx.x * blockDim.x + threadIdx.x;
    if (e < EE) atomicAdd(&g_dis[g_dst[e]], 1.0f);
}
__global__ void finalize_dis_k() {
    int i = blockIdx.x * blockDim.x + threadIdx.x;
    if (i < NN) g_dis[i] = rsqrtf(g_dis[i]);
}
__global__ void edge_norm_k() {
    int e = blockIdx.x * blockDim.x + threadIdx.x;
    if (e < EE) g_norm[e] = g_dis[g_src[e]] * g_dis[g_dst[e]];
}

// ---------------- aggregation-buffer init with self-loop term --------------
// g_aggx[i,f] = x[i,f] * dis[i]^2
__global__ void init_aggx_k(const float* __restrict__ x) {
    int tid = blockIdx.x * blockDim.x + threadIdx.x;
    if (tid >= NN * IN_DIM) return;
    int i = tid >> 8;  // /IN_DIM
    float dis = g_dis[i];
    g_aggx[tid] = x[tid] * dis * dis;
}
// g_agg2[i,f] = h2[i,f] * dis[i]^2
__global__ void init_agg2_k() {
    int tid = blockIdx.x * blockDim.x + threadIdx.x;
    if (tid >= NN * H2) return;
    int i = tid >> 7;  // /H2
    float dis = g_dis[i];
    g_agg2[tid] = g_h2[tid] * dis * dis;
}

// ---------------- edge aggregation ----------------
// LAYER 1: g_aggx[dst] += x[src] * norm   (F = 256, x passed as param)
// LAYER 2: g_agg2[dst] += g_h2[src] * norm (F = 128)
template <int LAYER>
__global__ void aggregate_k(const float* __restrict__ Xp) {
    constexpr int F = (LAYER == 1) ? IN_DIM : H2;
    const float* __restrict__ H = (LAYER == 1) ? Xp : g_h2;
    float* __restrict__ AGG     = (LAYER == 1) ? g_aggx : g_agg2;

    const int FC = F / 4;
    long long tid = (long long)blockIdx.x * blockDim.x + threadIdx.x;
    if (tid >= (long long)EE * FC) return;
    int e = (int)(tid / FC);
    int f = (int)(tid % FC) * 4;
    int s = g_src[e];
    int d = g_dst[e];
    float nrm = g_norm[e];
    float4 v = *reinterpret_cast<const float4*>(&H[(size_t)s * F + f]);
    float* o = &AGG[(size_t)d * F + f];
    atomicAdd(o + 0, v.x * nrm);
    atomicAdd(o + 1, v.y * nrm);
    atomicAdd(o + 2, v.z * nrm);
    atomicAdd(o + 3, v.w * nrm);
}

// ---------------- SGEMM: 128x128 tile, BK=16, 8x8 micro, double-buffered ----
// LAYER 1: A = g_aggx [NN x 256], B = W1 [256 x 512], C = g_h1
// LAYER 2: A = g_feat1 [NN x 512], B = W2 [512 x 128], C = g_h2
template <int LAYER>
__global__ void __launch_bounds__(256, 1) sgemm_k(const float* __restrict__ B) {
    constexpr int K  = (LAYER == 1) ? IN_DIM : H1;
    constexpr int Nc = (LAYER == 1) ? H1 : H2;
    constexpr int M  = NN;
    const float* __restrict__ A = (LAYER == 1) ? g_aggx : g_feat1;
    float* __restrict__ C       = (LAYER == 1) ? g_h1 : g_h2;

    constexpr int BM = 128, BN = 128, BK = 16;
    constexpr int NIT = K / BK;

    __shared__ float As[2][BK][BM + 4];
    __shared__ float Bs[2][BK][BN + 4];

    const int t = threadIdx.x;
    const int block_row = blockIdx.y * BM;
    const int block_col = blockIdx.x * BN;

    const int ar = t >> 2;            // 0..63  (A row within tile; +64 for 2nd)
    const int ak = (t & 3) << 2;      // 0,4,8,12
    const int bk = t >> 5;            // 0..7   (B k within tile; +8 for 2nd)
    const int bn = (t & 31) << 2;     // 0..124
    const int tx = t & 15;
    const int ty = t >> 4;

    float4 ra0, ra1, rb0, rb1;

    // prologue load (k0 = 0)
    {
        int r0 = block_row + ar, r1 = r0 + 64;
        ra0 = (r0 < M) ? *(const float4*)&A[(size_t)r0 * K + ak]
                       : make_float4(0.f, 0.f, 0.f, 0.f);
        ra1 = (r1 < M) ? *(const float4*)&A[(size_t)r1 * K + ak]
                       : make_float4(0.f, 0.f, 0.f, 0.f);
        rb0 = *(const float4*)&B[(size_t)bk * Nc + block_col + bn];
        rb1 = *(const float4*)&B[(size_t)(bk + 8) * Nc + block_col + bn];
    }
    {
        As[0][ak + 0][ar] = ra0.x; As[0][ak + 1][ar] = ra0.y;
        As[0][ak + 2][ar] = ra0.z; As[0][ak + 3][ar] = ra0.w;
        As[0][ak + 0][ar + 64] = ra1.x; As[0][ak + 1][ar + 64] = ra1.y;
        As[0][ak + 2][ar + 64] = ra1.z; As[0][ak + 3][ar + 64] = ra1.w;
        *(float4*)&Bs[0][bk][bn] = rb0;
        *(float4*)&Bs[0][bk + 8][bn] = rb1;
    }
    __syncthreads();

    float acc[8][8];
#pragma unroll
    for (int i = 0; i < 8; i++)
#pragma unroll
        for (int j = 0; j < 8; j++) acc[i][j] = 0.0f;

    for (int it = 0; it < NIT; it++) {
        const int buf = it & 1;
        const bool has_next = (it + 1 < NIT);
        if (has_next) {
            int k0 = (it + 1) * BK;
            int r0 = block_row + ar, r1 = r0 + 64;
            ra0 = (r0 < M) ? *(const float4*)&A[(size_t)r0 * K + k0 + ak]
                           : make_float4(0.f, 0.f, 0.f, 0.f);
            ra1 = (r1 < M) ? *(const float4*)&A[(size_t)r1 * K + k0 + ak]
                           : make_float4(0.f, 0.f, 0.f, 0.f);
            rb0 = *(const float4*)&B[(size_t)(k0 + bk) * Nc + block_col + bn];
            rb1 = *(const float4*)&B[(size_t)(k0 + bk + 8) * Nc + block_col + bn];
        }

#pragma unroll
        for (int kk = 0; kk < BK; kk++) {
            float4 a0 = *(const float4*)&As[buf][kk][ty * 8];
            float4 a1 = *(const float4*)&As[buf][kk][ty * 8 + 4];
            float4 b0 = *(const float4*)&Bs[buf][kk][tx * 8];
            float4 b1 = *(const float4*)&Bs[buf][kk][tx * 8 + 4];
            float av[8] = {a0.x, a0.y, a0.z, a0.w, a1.x, a1.y, a1.z, a1.w};
            float bv[8] = {b0.x, b0.y, b0.z, b0.w, b1.x, b1.y, b1.z, b1.w};
#pragma unroll
            for (int i = 0; i < 8; i++)
#pragma unroll
                for (int j = 0; j < 8; j++) acc[i][j] += av[i] * bv[j];
        }
        __syncthreads();
        if (has_next) {
            const int nb = buf ^ 1;
            As[nb][ak + 0][ar] = ra0.x; As[nb][ak + 1][ar] = ra0.y;
            As[nb][ak + 2][ar] = ra0.z; As[nb][ak + 3][ar] = ra0.w;
            As[nb][ak + 0][ar + 64] = ra1.x; As[nb][ak + 1][ar + 64] = ra1.y;
            As[nb][ak + 2][ar + 64] = ra1.z; As[nb][ak + 3][ar + 64] = ra1.w;
            *(float4*)&Bs[nb][bk][bn] = rb0;
            *(float4*)&Bs[nb][bk + 8][bn] = rb1;
            __syncthreads();
        }
    }

#pragma unroll
    for (int i = 0; i < 8; i++) {
        int row = block_row + ty * 8 + i;
        if (row < M) {
            float* cp = &C[(size_t)row * Nc + block_col + tx * 8];
            *(float4*)cp       = make_float4(acc[i][0], acc[i][1], acc[i][2], acc[i][3]);
            *(float4*)(cp + 4) = make_float4(acc[i][4], acc[i][5], acc[i][6], acc[i][7]);
        }
    }
}

// ---------------- epilogue: + bias, PReLU, dropout ----------------
// LAYER 1: in g_h1 -> out g_feat1     (self-loop already in aggregation)
// LAYER 2: in g_agg2 -> out param     (self-loop already in init_agg2)
template <int LAYER>
__global__ void epilogue_k(const float* __restrict__ bias,
                           const void* __restrict__ mask_raw,
                           const float* __restrict__ a_ptr,
                           float* __restrict__ out_param) {
    constexpr int F = (LAYER == 1) ? H1 : H2;
    const float* __restrict__ IN = (LAYER == 1) ? g_h1 : g_agg2;
    float* __restrict__ OUT      = (LAYER == 1) ? g_feat1 : out_param;

    int tid = blockIdx.x * blockDim.x + threadIdx.x;
    if (tid >= NN * F) return;
    int f = tid & (F - 1);
    float v = IN[tid] + bias[f];
    float a = __ldg(a_ptr);
    v = (v >= 0.0f) ? v : a * v;

    bool keep;
    int mk = g_mask_kind;
    if (mk == 1)      keep = ((const float*)mask_raw)[tid] != 0.0f;
    else if (mk == 2) keep = ((const int*)mask_raw)[tid] != 0;
    else if (mk == 3) keep = ((const long long*)mask_raw)[tid] != 0;
    else              keep = ((const unsigned char*)mask_raw)[tid] != 0;

    OUT[tid] = keep ? v * 2.0f : 0.0f;
}

// ---------------- launch (kernel launches only; graph-capturable) -----------
extern "C" void kernel_launch(void* const* d_in, const int* in_sizes, int n_in,
                              void* d_out, int out_size) {
    const float* x      = (const float*)d_in[0];
    const void*  ei_raw = d_in[1];
    const float* W1     = (const float*)d_in[2];
    const float* b1     = (const float*)d_in[3];
    const float* W2     = (const float*)d_in[4];
    const float* b2     = (const float*)d_in[5];
    const float* a      = (const float*)d_in[6];
    const void*  m1     = d_in[7];
    const void*  m2     = d_in[8];
    float* out          = (float*)d_out;

    const int T = 256;

    // prep
    detect_dtype_k<<<1, 1>>>(ei_raw, m1);
    convert_edges_k<<<(EE + T - 1) / T, T>>>(ei_raw);
    init_deg_k<<<(NN + T - 1) / T, T>>>();
    deg_accum_k<<<(EE + T - 1) / T, T>>>();
    finalize_dis_k<<<(NN + T - 1) / T, T>>>();
    edge_norm_k<<<(EE + T - 1) / T, T>>>();

    // ---- layer 1: aggregate x first (256 feats), then GEMM ----
    init_aggx_k<<<(NN * IN_DIM + T - 1) / T, T>>>(x);
    {
        long long work = (long long)EE * (IN_DIM / 4);
        aggregate_k<1><<<(int)((work + T - 1) / T), T>>>(x);
    }
    {
        dim3 grid(H1 / 128, (NN + 127) / 128);
        sgemm_k<1><<<grid, 256>>>(W1);
    }
    epilogue_k<1><<<(NN * H1 + T - 1) / T, T>>>(b1, m1, a, nullptr);

    // ---- layer 2: GEMM first, aggregate on 128 feats ----
    {
        dim3 grid(H2 / 128, (NN + 127) / 128);
        sgemm_k<2><<<grid, 256>>>(W2);
    }
    init_agg2_k<<<(NN * H2 + T - 1) / T, T>>>();
    {
        long long work = (long long)EE * (H2 / 4);
        aggregate_k<2><<<(int)((work + T - 1) / T), T>>>(nullptr);
    }
    epilogue_k<2><<<(NN * H2 + T - 1) / T, T>>>(b2, m2, a, out);
}

// round 9
// speedup vs baseline: 1.8195x; 1.2808x over previous
#include <cuda_runtime.h>
#include <cuda_bf16.h>
#include <mma.h>
#include <stdint.h>

using namespace nvcuda;

#define NN 50000
#define NN_PAD 50048   // multiple of 128; padding rows stay zero (.bss)
#define EE 400000
#define IN_DIM 256
#define H1 512
#define H2 128

// ---------------- scratch (device globals; device-side references only) -----
__device__ int   g_is64;
__device__ int   g_mask_kind;                 // 0=u8, 1=f32, 2=i32, 3=i64
__device__ int   g_src[EE];
__device__ int   g_dst[EE];
__device__ float g_norm[EE];
__device__ float g_dis[NN];
__device__ float g_aggx[(size_t)NN_PAD * IN_DIM];  // aggregated x (padded)
__device__ float g_h1[(size_t)NN_PAD * H1];        // aggx @ W1 (padded)
__device__ float g_feat1[(size_t)NN_PAD * H1];     // post-epilogue1 (padded)
__device__ float g_h2[(size_t)NN_PAD * H2];        // feat1 @ W2 (padded)
__device__ float g_agg2[(size_t)NN * H2];          // aggregated layer 2

// ---------------- dtype detection ----------------
__global__ void detect_dtype_k(const void* ei_raw, const void* mask_raw) {
    const long long* e64 = (const long long*)ei_raw;
    int ok64 = 1;
    for (int i = 0; i < 256; i++) {
        long long v = e64[i];
        if (v < 0 || v >= NN) { ok64 = 0; break; }
    }
    g_is64 = ok64;

    const unsigned* mw = (const unsigned*)mask_raw;
    int all_f32 = 1, all_01 = 1, odd_zero = 1;
    for (int i = 0; i < 256; i++) {
        unsigned v = mw[i];
        if (v != 0u && v != 0x3F800000u) all_f32 = 0;
        if (v > 1u) all_01 = 0;
        if ((i & 1) && v != 0u) odd_zero = 0;
    }
    if (all_f32)                 g_mask_kind = 1;
    else if (all_01 && odd_zero) g_mask_kind = 3;
    else if (all_01)             g_mask_kind = 2;
    else                         g_mask_kind = 0;
}

__global__ void convert_edges_k(const void* ei_raw) {
    int e = blockIdx.x * blockDim.x + threadIdx.x;
    if (e >= EE) return;
    if (g_is64) {
        const long long* e64 = (const long long*)ei_raw;
        g_src[e] = (int)e64[e];
        g_dst[e] = (int)e64[EE + e];
    } else {
        const int* e32 = (const int*)ei_raw;
        g_src[e] = e32[e];
        g_dst[e] = e32[EE + e];
    }
}

// ---------------- degree / normalization ----------------
__global__ void init_deg_k() {
    int i = blockIdx.x * blockDim.x + threadIdx.x;
    if (i < NN) g_dis[i] = 1.0f;
}
__global__ void deg_accum_k() {
    int e = blockIdx.x * blockDim.x + threadIdx.x;
    if (e < EE) atomicAdd(&g_dis[g_dst[e]], 1.0f);
}
__global__ void finalize_dis_k() {
    int i = blockIdx.x * blockDim.x + threadIdx.x;
    if (i < NN) g_dis[i] = rsqrtf(g_dis[i]);
}
__global__ void edge_norm_k() {
    int e = blockIdx.x * blockDim.x + threadIdx.x;
    if (e < EE) g_norm[e] = g_dis[g_src[e]] * g_dis[g_dst[e]];
}

// ---------------- aggregation-buffer init with self-loop term --------------
__global__ void init_aggx_k(const float* __restrict__ x) {
    int tid = blockIdx.x * blockDim.x + threadIdx.x;
    if (tid >= NN * IN_DIM) return;
    int i = tid >> 8;
    float dis = g_dis[i];
    g_aggx[tid] = x[tid] * dis * dis;
}
__global__ void init_agg2_k() {
    int tid = blockIdx.x * blockDim.x + threadIdx.x;
    if (tid >= NN * H2) return;
    int i = tid >> 7;
    float dis = g_dis[i];
    g_agg2[tid] = g_h2[tid] * dis * dis;
}

// ---------------- edge aggregation ----------------
template <int LAYER>
__global__ void aggregate_k(const float* __restrict__ Xp) {
    constexpr int F = (LAYER == 1) ? IN_DIM : H2;
    const float* __restrict__ H = (LAYER == 1) ? Xp : g_h2;
    float* __restrict__ AGG     = (LAYER == 1) ? g_aggx : g_agg2;

    const int FC = F / 4;
    long long tid = (long long)blockIdx.x * blockDim.x + threadIdx.x;
    if (tid >= (long long)EE * FC) return;
    int e = (int)(tid / FC);
    int f = (int)(tid % FC) * 4;
    int s = g_src[e];
    int d = g_dst[e];
    float nrm = g_norm[e];
    float4 v = *reinterpret_cast<const float4*>(&H[(size_t)s * F + f]);
    float* o = &AGG[(size_t)d * F + f];
    atomicAdd(o + 0, v.x * nrm);
    atomicAdd(o + 1, v.y * nrm);
    atomicAdd(o + 2, v.z * nrm);
    atomicAdd(o + 3, v.w * nrm);
}

// ---------------- TF32 WMMA GEMM: C = A @ B ----------------
// 128x128 tile, BK=16, 8 warps (2x4), warp tile 64x32 = 4x2 wmma m16n16k8.
// A is padded to NN_PAD rows -> no row guards anywhere.
// LAYER 1: A = g_aggx [NN_PAD x 256], B = W1 [256 x 512], C = g_h1
// LAYER 2: A = g_feat1 [NN_PAD x 512], B = W2 [512 x 128], C = g_h2
template <int LAYER>
__global__ void __launch_bounds__(256, 2) wgemm_k(const float* __restrict__ B) {
    constexpr int K  = (LAYER == 1) ? IN_DIM : H1;
    constexpr int Nc = (LAYER == 1) ? H1 : H2;
    const float* __restrict__ A = (LAYER == 1) ? g_aggx : g_feat1;
    float* __restrict__ C       = (LAYER == 1) ? g_h1 : g_h2;

    constexpr int BM = 128, BN = 128, BK = 16;
    constexpr int NIT = K / BK;
    constexpr int LDA = BK + 4;    // 20
    constexpr int LDB = BN + 4;    // 132

    __shared__ float As[2][BM][LDA];
    __shared__ float Bs[2][BK][LDB];

    const int t = threadIdx.x;
    const int warp = t >> 5;
    const int wr = warp >> 2;          // 0..1  -> row offset wr*64
    const int wc = warp & 3;           // 0..3  -> col offset wc*32
    const size_t block_row = (size_t)blockIdx.y * BM;
    const int    block_col = blockIdx.x * BN;

    // load mapping: A tile 128x16 -> t>>1 = row, (t&1)*8 = col (2 float4)
    //               B tile 16x128 -> t>>4 = row, (t&15)*8 = col (2 float4)
    const int a_r = t >> 1, a_c = (t & 1) << 3;
    const int b_r = t >> 4, b_c = (t & 15) << 3;

    float4 ra0, ra1, rb0, rb1;
    {
        const float* ap = &A[(block_row + a_r) * K + a_c];
        ra0 = *(const float4*)ap; ra1 = *(const float4*)(ap + 4);
        const float* bp = &B[(size_t)b_r * Nc + block_col + b_c];
        rb0 = *(const float4*)bp; rb1 = *(const float4*)(bp + 4);
    }
    *(float4*)&As[0][a_r][a_c]     = ra0;
    *(float4*)&As[0][a_r][a_c + 4] = ra1;
    *(float4*)&Bs[0][b_r][b_c]     = rb0;
    *(float4*)&Bs[0][b_r][b_c + 4] = rb1;
    __syncthreads();

    wmma::fragment<wmma::accumulator, 16, 16, 8, float> acc[4][2];
#pragma unroll
    for (int i = 0; i < 4; i++)
#pragma unroll
        for (int j = 0; j < 2; j++) wmma::fill_fragment(acc[i][j], 0.0f);

    for (int it = 0; it < NIT; it++) {
        const int buf = it & 1;
        const bool has_next = (it + 1 < NIT);
        if (has_next) {
            const int k0 = (it + 1) * BK;
            const float* ap = &A[(block_row + a_r) * K + k0 + a_c];
            ra0 = *(const float4*)ap; ra1 = *(const float4*)(ap + 4);
            const float* bp = &B[(size_t)(k0 + b_r) * Nc + block_col + b_c];
            rb0 = *(const float4*)bp; rb1 = *(const float4*)(bp + 4);
        }

#pragma unroll
        for (int ks = 0; ks < 2; ks++) {  // two k=8 steps per BK=16
            wmma::fragment<wmma::matrix_a, 16, 16, 8, wmma::precision::tf32, wmma::row_major> fa[4];
            wmma::fragment<wmma::matrix_b, 16, 16, 8, wmma::precision::tf32, wmma::row_major> fb[2];
#pragma unroll
            for (int i = 0; i < 4; i++) {
                wmma::load_matrix_sync(fa[i], &As[buf][wr * 64 + i * 16][ks * 8], LDA);
#pragma unroll
                for (int e = 0; e < fa[i].num_elements; e++)
                    fa[i].x[e] = wmma::__float_to_tf32(fa[i].x[e]);
            }
#pragma unroll
            for (int j = 0; j < 2; j++) {
                wmma::load_matrix_sync(fb[j], &Bs[buf][ks * 8][wc * 32 + j * 16], LDB);
#pragma unroll
                for (int e = 0; e < fb[j].num_elements; e++)
                    fb[j].x[e] = wmma::__float_to_tf32(fb[j].x[e]);
            }
#pragma unroll
            for (int i = 0; i < 4; i++)
#pragma unroll
                for (int j = 0; j < 2; j++)
                    wmma::mma_sync(acc[i][j], fa[i], fb[j], acc[i][j]);
        }

        __syncthreads();
        if (has_next) {
            const int nb = buf ^ 1;
            *(float4*)&As[nb][a_r][a_c]     = ra0;
            *(float4*)&As[nb][a_r][a_c + 4] = ra1;
            *(float4*)&Bs[nb][b_r][b_c]     = rb0;
            *(float4*)&Bs[nb][b_r][b_c + 4] = rb1;
            __syncthreads();
        }
    }

    // store (C padded -> no guards)
#pragma unroll
    for (int i = 0; i < 4; i++)
#pragma unroll
        for (int j = 0; j < 2; j++) {
            float* cp = &C[(block_row + wr * 64 + i * 16) * Nc
                           + block_col + wc * 32 + j * 16];
            wmma::store_matrix_sync(cp, acc[i][j], Nc, wmma::mem_row_major);
        }
}

// ---------------- epilogue: + bias, PReLU, dropout ----------------
template <int LAYER>
__global__ void epilogue_k(const float* __restrict__ bias,
                           const void* __restrict__ mask_raw,
                           const float* __restrict__ a_ptr,
                           float* __restrict__ out_param) {
    constexpr int F = (LAYER == 1) ? H1 : H2;
    const float* __restrict__ IN = (LAYER == 1) ? g_h1 : g_agg2;
    float* __restrict__ OUT      = (LAYER == 1) ? g_feat1 : out_param;

    int tid = blockIdx.x * blockDim.x + threadIdx.x;
    if (tid >= NN * F) return;
    int f = tid & (F - 1);
    float v = IN[tid] + bias[f];
    float a = __ldg(a_ptr);
    v = (v >= 0.0f) ? v : a * v;

    bool keep;
    int mk = g_mask_kind;
    if (mk == 1)      keep = ((const float*)mask_raw)[tid] != 0.0f;
    else if (mk == 2) keep = ((const int*)mask_raw)[tid] != 0;
    else if (mk == 3) keep = ((const long long*)mask_raw)[tid] != 0;
    else              keep = ((const unsigned char*)mask_raw)[tid] != 0;

    OUT[tid] = keep ? v * 2.0f : 0.0f;
}

// ---------------- launch (kernel launches only; graph-capturable) -----------
extern "C" void kernel_launch(void* const* d_in, const int* in_sizes, int n_in,
                              void* d_out, int out_size) {
    const float* x      = (const float*)d_in[0];
    const void*  ei_raw = d_in[1];
    const float* W1     = (const float*)d_in[2];
    const float* b1     = (const float*)d_in[3];
    const float* W2     = (const float*)d_in[4];
    const float* b2     = (const float*)d_in[5];
    const float* a      = (const float*)d_in[6];
    const void*  m1     = d_in[7];
    const void*  m2     = d_in[8];
    float* out          = (float*)d_out;

    const int T = 256;

    // prep
    detect_dtype_k<<<1, 1>>>(ei_raw, m1);
    convert_edges_k<<<(EE + T - 1) / T, T>>>(ei_raw);
    init_deg_k<<<(NN + T - 1) / T, T>>>();
    deg_accum_k<<<(EE + T - 1) / T, T>>>();
    finalize_dis_k<<<(NN + T - 1) / T, T>>>();
    edge_norm_k<<<(EE + T - 1) / T, T>>>();

    // ---- layer 1: aggregate x first (256 feats), then TF32 GEMM ----
    init_aggx_k<<<(NN * IN_DIM + T - 1) / T, T>>>(x);
    {
        long long work = (long long)EE * (IN_DIM / 4);
        aggregate_k<1><<<(int)((work + T - 1) / T), T>>>(x);
    }
    {
        dim3 grid(H1 / 128, NN_PAD / 128);
        wgemm_k<1><<<grid, 256>>>(W1);
    }
    epilogue_k<1><<<(NN * H1 + T - 1) / T, T>>>(b1, m1, a, nullptr);

    // ---- layer 2: TF32 GEMM first, aggregate on 128 feats ----
    {
        dim3 grid(H2 / 128, NN_PAD / 128);
        wgemm_k<2><<<grid, 256>>>(W2);
    }
    init_agg2_k<<<(NN * H2 + T - 1) / T, T>>>();
    {
        long long work = (long long)EE * (H2 / 4);
        aggregate_k<2><<<(int)((work + T - 1) / T), T>>>(nullptr);
    }
    epilogue_k<2><<<(NN * H2 + T - 1) / T, T>>>(b2, m2, a, out);
}

// round 10
// speedup vs baseline: 2.5174x; 1.3836x over previous
#include <cuda_runtime.h>
#include <cuda_bf16.h>
#include <mma.h>
#include <stdint.h>

using namespace nvcuda;

#define NN 50000
#define NN_PAD 50048   // multiple of 128; padding rows stay zero (.bss)
#define EE 400000
#define IN_DIM 256
#define H1 512
#define H2 128

// ---------------- scratch (device globals; device-side references only) -----
__device__ int   g_is64;
__device__ int   g_mask_kind;                 // 0=u8, 1=f32, 2=i32, 3=i64
__device__ int   g_src[EE];
__device__ int   g_dst[EE];
__device__ int   g_cnt[NN];                   // in-degree (excl self)
__device__ int   g_rowptr[NN + 1];            // CSR row pointers (by dst)
__device__ int   g_cursor[NN];                // scatter cursors
__device__ int   g_es[EE];                    // CSR: src indices sorted by dst
__device__ float g_dis[NN];                   // rsqrt(deg incl self)
__device__ float g_aggx[(size_t)NN_PAD * IN_DIM];  // aggregated x (padded)
__device__ float g_h1[(size_t)NN_PAD * H1];        // aggx @ W1 (padded)
__device__ float g_feat1[(size_t)NN_PAD * H1];     // post-epilogue1 (padded)
__device__ float g_h2[(size_t)NN_PAD * H2];        // feat1 @ W2 (padded)

// ---------------- dtype detection ----------------
__global__ void detect_dtype_k(const void* ei_raw, const void* mask_raw) {
    const long long* e64 = (const long long*)ei_raw;
    int ok64 = 1;
    for (int i = 0; i < 256; i++) {
        long long v = e64[i];
        if (v < 0 || v >= NN) { ok64 = 0; break; }
    }
    g_is64 = ok64;

    const unsigned* mw = (const unsigned*)mask_raw;
    int all_f32 = 1, all_01 = 1, odd_zero = 1;
    for (int i = 0; i < 256; i++) {
        unsigned v = mw[i];
        if (v != 0u && v != 0x3F800000u) all_f32 = 0;
        if (v > 1u) all_01 = 0;
        if ((i & 1) && v != 0u) odd_zero = 0;
    }
    if (all_f32)                 g_mask_kind = 1;
    else if (all_01 && odd_zero) g_mask_kind = 3;
    else if (all_01)             g_mask_kind = 2;
    else                         g_mask_kind = 0;
}

__global__ void convert_edges_k(const void* ei_raw) {
    int e = blockIdx.x * blockDim.x + threadIdx.x;
    if (e >= EE) return;
    if (g_is64) {
        const long long* e64 = (const long long*)ei_raw;
        g_src[e] = (int)e64[e];
        g_dst[e] = (int)e64[EE + e];
    } else {
        const int* e32 = (const int*)ei_raw;
        g_src[e] = e32[e];
        g_dst[e] = e32[EE + e];
    }
}

// ---------------- CSR build ----------------
__global__ void zero_cnt_k() {
    int i = blockIdx.x * blockDim.x + threadIdx.x;
    if (i < NN) g_cnt[i] = 0;
}
__global__ void hist_k() {
    int e = blockIdx.x * blockDim.x + threadIdx.x;
    if (e < EE) atomicAdd(&g_cnt[g_dst[e]], 1);
}
// single-block scan over 50000 counts; also finalizes dis = rsqrt(cnt+1)
__global__ void scan_k() {
    __shared__ int sums[1024];
    const int t = threadIdx.x;
    const int PER = (NN + 1023) / 1024;   // 49
    const int base = t * PER;

    int local = 0;
    for (int k = 0; k < PER; k++) {
        int idx = base + k;
        if (idx < NN) local += g_cnt[idx];
    }
    sums[t] = local;
    __syncthreads();
    for (int off = 1; off < 1024; off <<= 1) {
        int v = (t >= off) ? sums[t - off] : 0;
        __syncthreads();
        if (t >= off) sums[t] += v;
        __syncthreads();
    }
    int run = (t > 0) ? sums[t - 1] : 0;
    for (int k = 0; k < PER; k++) {
        int idx = base + k;
        if (idx < NN) {
            g_rowptr[idx] = run;
            g_cursor[idx] = run;
            int c = g_cnt[idx];
            g_dis[idx] = rsqrtf((float)(c + 1));   // + self-loop
            run += c;
        }
    }
    if (t == 1023) g_rowptr[NN] = sums[1023];
}
__global__ void scatter_k() {
    int e = blockIdx.x * blockDim.x + threadIdx.x;
    if (e >= EE) return;
    int d = g_dst[e];
    int pos = atomicAdd(&g_cursor[d], 1);
    g_es[pos] = g_src[e];
}

// ---------------- layer-1 aggregation: warp per node, F=256 ----------------
// g_aggx[d] = x[d]*dis[d]^2 + sum_{s->d} x[s]*dis[s]*dis[d]
__global__ void agg1_k(const float* __restrict__ x) {
    int node = (blockIdx.x * blockDim.x + threadIdx.x) >> 5;
    if (node >= NN) return;
    const int lane = threadIdx.x & 31;

    const float disd = g_dis[node];
    const float4* xs = (const float4*)&x[(size_t)node * IN_DIM];
    float4 a0 = xs[lane], a1 = xs[lane + 32];
    const float self = disd * disd;
    a0.x *= self; a0.y *= self; a0.z *= self; a0.w *= self;
    a1.x *= self; a1.y *= self; a1.z *= self; a1.w *= self;

    const int beg = g_rowptr[node], end = g_rowptr[node + 1];
    for (int j = beg; j < end; j++) {
        int s = g_es[j];
        float nrm = g_dis[s] * disd;
        const float4* hs = (const float4*)&x[(size_t)s * IN_DIM];
        float4 v0 = hs[lane], v1 = hs[lane + 32];
        a0.x += v0.x * nrm; a0.y += v0.y * nrm; a0.z += v0.z * nrm; a0.w += v0.w * nrm;
        a1.x += v1.x * nrm; a1.y += v1.y * nrm; a1.z += v1.z * nrm; a1.w += v1.w * nrm;
    }
    float4* o = (float4*)&g_aggx[(size_t)node * IN_DIM];
    o[lane] = a0;
    o[lane + 32] = a1;
}

// ---------------- TF32 WMMA GEMM: C = A @ B (unchanged from round 9) --------
template <int LAYER>
__global__ void __launch_bounds__(256, 2) wgemm_k(const float* __restrict__ B) {
    constexpr int K  = (LAYER == 1) ? IN_DIM : H1;
    constexpr int Nc = (LAYER == 1) ? H1 : H2;
    const float* __restrict__ A = (LAYER == 1) ? g_aggx : g_feat1;
    float* __restrict__ C       = (LAYER == 1) ? g_h1 : g_h2;

    constexpr int BM = 128, BN = 128, BK = 16;
    constexpr int NIT = K / BK;
    constexpr int LDA = BK + 4;
    constexpr int LDB = BN + 4;

    __shared__ float As[2][BM][LDA];
    __shared__ float Bs[2][BK][LDB];

    const int t = threadIdx.x;
    const int warp = t >> 5;
    const int wr = warp >> 2;
    const int wc = warp & 3;
    const size_t block_row = (size_t)blockIdx.y * BM;
    const int    block_col = blockIdx.x * BN;

    const int a_r = t >> 1, a_c = (t & 1) << 3;
    const int b_r = t >> 4, b_c = (t & 15) << 3;

    float4 ra0, ra1, rb0, rb1;
    {
        const float* ap = &A[(block_row + a_r) * K + a_c];
        ra0 = *(const float4*)ap; ra1 = *(const float4*)(ap + 4);
        const float* bp = &B[(size_t)b_r * Nc + block_col + b_c];
        rb0 = *(const float4*)bp; rb1 = *(const float4*)(bp + 4);
    }
    *(float4*)&As[0][a_r][a_c]     = ra0;
    *(float4*)&As[0][a_r][a_c + 4] = ra1;
    *(float4*)&Bs[0][b_r][b_c]     = rb0;
    *(float4*)&Bs[0][b_r][b_c + 4] = rb1;
    __syncthreads();

    wmma::fragment<wmma::accumulator, 16, 16, 8, float> acc[4][2];
#pragma unroll
    for (int i = 0; i < 4; i++)
#pragma unroll
        for (int j = 0; j < 2; j++) wmma::fill_fragment(acc[i][j], 0.0f);

    for (int it = 0; it < NIT; it++) {
        const int buf = it & 1;
        const bool has_next = (it + 1 < NIT);
        if (has_next) {
            const int k0 = (it + 1) * BK;
            const float* ap = &A[(block_row + a_r) * K + k0 + a_c];
            ra0 = *(const float4*)ap; ra1 = *(const float4*)(ap + 4);
            const float* bp = &B[(size_t)(k0 + b_r) * Nc + block_col + b_c];
            rb0 = *(const float4*)bp; rb1 = *(const float4*)(bp + 4);
        }

#pragma unroll
        for (int ks = 0; ks < 2; ks++) {
            wmma::fragment<wmma::matrix_a, 16, 16, 8, wmma::precision::tf32, wmma::row_major> fa[4];
            wmma::fragment<wmma::matrix_b, 16, 16, 8, wmma::precision::tf32, wmma::row_major> fb[2];
#pragma unroll
            for (int i = 0; i < 4; i++) {
                wmma::load_matrix_sync(fa[i], &As[buf][wr * 64 + i * 16][ks * 8], LDA);
#pragma unroll
                for (int e = 0; e < fa[i].num_elements; e++)
                    fa[i].x[e] = wmma::__float_to_tf32(fa[i].x[e]);
            }
#pragma unroll
            for (int j = 0; j < 2; j++) {
                wmma::load_matrix_sync(fb[j], &Bs[buf][ks * 8][wc * 32 + j * 16], LDB);
#pragma unroll
                for (int e = 0; e < fb[j].num_elements; e++)
                    fb[j].x[e] = wmma::__float_to_tf32(fb[j].x[e]);
            }
#pragma unroll
            for (int i = 0; i < 4; i++)
#pragma unroll
                for (int j = 0; j < 2; j++)
                    wmma::mma_sync(acc[i][j], fa[i], fb[j], acc[i][j]);
        }

        __syncthreads();
        if (has_next) {
            const int nb = buf ^ 1;
            *(float4*)&As[nb][a_r][a_c]     = ra0;
            *(float4*)&As[nb][a_r][a_c + 4] = ra1;
            *(float4*)&Bs[nb][b_r][b_c]     = rb0;
            *(float4*)&Bs[nb][b_r][b_c + 4] = rb1;
            __syncthreads();
        }
    }

#pragma unroll
    for (int i = 0; i < 4; i++)
#pragma unroll
        for (int j = 0; j < 2; j++) {
            float* cp = &C[(block_row + wr * 64 + i * 16) * Nc
                           + block_col + wc * 32 + j * 16];
            wmma::store_matrix_sync(cp, acc[i][j], Nc, wmma::mem_row_major);
        }
}

// ---------------- epilogue 1: bias + PReLU + dropout -> g_feat1 -------------
__global__ void epilogue1_k(const float* __restrict__ bias,
                            const void* __restrict__ mask_raw,
                            const float* __restrict__ a_ptr) {
    int tid = blockIdx.x * blockDim.x + threadIdx.x;
    if (tid >= NN * H1) return;
    int f = tid & (H1 - 1);
    float v = g_h1[tid] + bias[f];
    float a = __ldg(a_ptr);
    v = (v >= 0.0f) ? v : a * v;

    bool keep;
    int mk = g_mask_kind;
    if (mk == 1)      keep = ((const float*)mask_raw)[tid] != 0.0f;
    else if (mk == 2) keep = ((const int*)mask_raw)[tid] != 0;
    else if (mk == 3) keep = ((const long long*)mask_raw)[tid] != 0;
    else              keep = ((const unsigned char*)mask_raw)[tid] != 0;

    g_feat1[tid] = keep ? v * 2.0f : 0.0f;
}

// ---------------- layer-2 aggregation FUSED with epilogue 2 ------------------
// out[d] = dropout(prelu(h2[d]*dis^2 + sum h2[s]*nrm + b2))
__global__ void agg2_fused_k(const float* __restrict__ bias,
                             const void* __restrict__ mask_raw,
                             const float* __restrict__ a_ptr,
                             float* __restrict__ out) {
    int node = (blockIdx.x * blockDim.x + threadIdx.x) >> 5;
    if (node >= NN) return;
    const int lane = threadIdx.x & 31;

    const float disd = g_dis[node];
    const float4* hs = (const float4*)&g_h2[(size_t)node * H2];
    float4 acc = hs[lane];
    const float self = disd * disd;
    acc.x *= self; acc.y *= self; acc.z *= self; acc.w *= self;

    const int beg = g_rowptr[node], end = g_rowptr[node + 1];
    for (int j = beg; j < end; j++) {
        int s = g_es[j];
        float nrm = g_dis[s] * disd;
        const float4* vs = (const float4*)&g_h2[(size_t)s * H2];
        float4 v = vs[lane];
        acc.x += v.x * nrm; acc.y += v.y * nrm; acc.z += v.z * nrm; acc.w += v.w * nrm;
    }

    // bias + PReLU
    const float4 b = *(const float4*)&bias[lane * 4];
    const float a = __ldg(a_ptr);
    acc.x += b.x; acc.y += b.y; acc.z += b.z; acc.w += b.w;
    acc.x = (acc.x >= 0.0f) ? acc.x : a * acc.x;
    acc.y = (acc.y >= 0.0f) ? acc.y : a * acc.y;
    acc.z = (acc.z >= 0.0f) ? acc.z : a * acc.z;
    acc.w = (acc.w >= 0.0f) ? acc.w : a * acc.w;

    // dropout mask at [node*128 + lane*4 .. +3]
    const size_t mi = (size_t)node * H2 + lane * 4;
    bool k0, k1, k2, k3;
    int mk = g_mask_kind;
    if (mk == 1) {
        float4 m = *(const float4*)&((const float*)mask_raw)[mi];
        k0 = m.x != 0.0f; k1 = m.y != 0.0f; k2 = m.z != 0.0f; k3 = m.w != 0.0f;
    } else if (mk == 2) {
        int4 m = *(const int4*)&((const int*)mask_raw)[mi];
        k0 = m.x != 0; k1 = m.y != 0; k2 = m.z != 0; k3 = m.w != 0;
    } else if (mk == 3) {
        const long long* m = &((const long long*)mask_raw)[mi];
        k0 = m[0] != 0; k1 = m[1] != 0; k2 = m[2] != 0; k3 = m[3] != 0;
    } else {
        uchar4 m = *(const uchar4*)&((const unsigned char*)mask_raw)[mi];
        k0 = m.x != 0; k1 = m.y != 0; k2 = m.z != 0; k3 = m.w != 0;
    }
    acc.x = k0 ? acc.x * 2.0f : 0.0f;
    acc.y = k1 ? acc.y * 2.0f : 0.0f;
    acc.z = k2 ? acc.z * 2.0f : 0.0f;
    acc.w = k3 ? acc.w * 2.0f : 0.0f;

    *(float4*)&out[(size_t)node * H2 + lane * 4] = acc;
}

// ---------------- launch (kernel launches only; graph-capturable) -----------
extern "C" void kernel_launch(void* const* d_in, const int* in_sizes, int n_in,
                              void* d_out, int out_size) {
    const float* x      = (const float*)d_in[0];
    const void*  ei_raw = d_in[1];
    const float* W1     = (const float*)d_in[2];
    const float* b1     = (const float*)d_in[3];
    const float* W2     = (const float*)d_in[4];
    const float* b2     = (const float*)d_in[5];
    const float* a      = (const float*)d_in[6];
    const void*  m1     = d_in[7];
    const void*  m2     = d_in[8];
    float* out          = (float*)d_out;

    const int T = 256;

    // prep: dtype detect, edges, CSR, dis
    detect_dtype_k<<<1, 1>>>(ei_raw, m1);
    convert_edges_k<<<(EE + T - 1) / T, T>>>(ei_raw);
    zero_cnt_k<<<(NN + T - 1) / T, T>>>();
    hist_k<<<(EE + T - 1) / T, T>>>();
    scan_k<<<1, 1024>>>();
    scatter_k<<<(EE + T - 1) / T, T>>>();

    // ---- layer 1: CSR aggregate x (256 feats), TF32 GEMM, epilogue ----
    agg1_k<<<(NN * 32 + T - 1) / T, T>>>(x);
    {
        dim3 grid(H1 / 128, NN_PAD / 128);
        wgemm_k<1><<<grid, 256>>>(W1);
    }
    epilogue1_k<<<(NN * H1 + T - 1) / T, T>>>(b1, m1, a);

    // ---- layer 2: TF32 GEMM, then fused aggregate+epilogue -> out ----
    {
        dim3 grid(H2 / 128, NN_PAD / 128);
        wgemm_k<2><<<grid, 256>>>(W2);
    }
    agg2_fused_k<<<(NN * 32 + T - 1) / T, T>>>(b2, m2, a, out);
}

// round 13
// speedup vs baseline: 2.8170x; 1.1190x over previous
#include <cuda_runtime.h>
#include <cuda_bf16.h>
#include <mma.h>
#include <stdint.h>

using namespace nvcuda;

#define NN 50000
#define NN_PAD 50048   // multiple of 128; padding rows stay zero (.bss)
#define EE 400000
#define IN_DIM 256
#define H1 512
#define H2 128

// ---------------- scratch (device globals; device-side references only) -----
__device__ int   g_mask_kind;                 // 0=u8, 1=f32, 2=i32, 3=i64
__device__ int   g_src[EE];
__device__ int   g_dst[EE];
__device__ int   g_cnt[NN];                   // in-degree (excl self)
__device__ int   g_rowptr[NN + 1];            // CSR row pointers (by dst)
__device__ int   g_cursor[NN];                // scatter cursors
__device__ int   g_es[EE];                    // CSR: src indices sorted by dst
__device__ float g_dis[NN];                   // rsqrt(deg incl self)
__device__ float g_aggx[(size_t)NN_PAD * IN_DIM];  // aggregated x (padded)
__device__ float g_feat1[(size_t)NN_PAD * H1];     // post-epilogue1 (padded)
__device__ float g_h2[(size_t)NN_PAD * H2];        // feat1 @ W2 (padded)

// ---------------- prep: dtype detect + edge convert + cnt zero --------------
__global__ void prep_k(const void* ei_raw, const void* mask_raw) {
    __shared__ int s_is64;
    const int tid = blockIdx.x * blockDim.x + threadIdx.x;

    if (threadIdx.x == 0) {
        const long long* e64 = (const long long*)ei_raw;
        int ok64 = 1;
        for (int i = 0; i < 256; i++) {
            long long v = e64[i];
            if (v < 0 || v >= NN) { ok64 = 0; break; }
        }
        s_is64 = ok64;

        if (blockIdx.x == 0) {
            const unsigned* mw = (const unsigned*)mask_raw;
            int all_f32 = 1, all_01 = 1, odd_zero = 1;
            for (int i = 0; i < 256; i++) {
                unsigned v = mw[i];
                if (v != 0u && v != 0x3F800000u) all_f32 = 0;
                if (v > 1u) all_01 = 0;
                if ((i & 1) && v != 0u) odd_zero = 0;
            }
            if (all_f32)                 g_mask_kind = 1;
            else if (all_01 && odd_zero) g_mask_kind = 3;
            else if (all_01)             g_mask_kind = 2;
            else                         g_mask_kind = 0;
        }
    }
    __syncthreads();

    if (tid < NN) g_cnt[tid] = 0;
    if (tid < EE) {
        if (s_is64) {
            const long long* e64 = (const long long*)ei_raw;
            g_src[tid] = (int)e64[tid];
            g_dst[tid] = (int)e64[EE + tid];
        } else {
            const int* e32 = (const int*)ei_raw;
            g_src[tid] = e32[tid];
            g_dst[tid] = e32[EE + tid];
        }
    }
}

// ---------------- CSR build ----------------
__global__ void hist_k() {
    int e = blockIdx.x * blockDim.x + threadIdx.x;
    if (e < EE) atomicAdd(&g_cnt[g_dst[e]], 1);
}
__global__ void scan_k() {
    __shared__ int sums[1024];
    const int t = threadIdx.x;
    const int PER = (NN + 1023) / 1024;   // 49
    const int base = t * PER;

    int local = 0;
    for (int k = 0; k < PER; k++) {
        int idx = base + k;
        if (idx < NN) local += g_cnt[idx];
    }
    sums[t] = local;
    __syncthreads();
    for (int off = 1; off < 1024; off <<= 1) {
        int v = (t >= off) ? sums[t - off] : 0;
        __syncthreads();
        if (t >= off) sums[t] += v;
        __syncthreads();
    }
    int run = (t > 0) ? sums[t - 1] : 0;
    for (int k = 0; k < PER; k++) {
        int idx = base + k;
        if (idx < NN) {
            g_rowptr[idx] = run;
            g_cursor[idx] = run;
            int c = g_cnt[idx];
            g_dis[idx] = rsqrtf((float)(c + 1));   // + self-loop
            run += c;
        }
    }
    if (t == 1023) g_rowptr[NN] = sums[1023];
}
__global__ void scatter_k() {
    int e = blockIdx.x * blockDim.x + threadIdx.x;
    if (e >= EE) return;
    int d = g_dst[e];
    int pos = atomicAdd(&g_cursor[d], 1);
    g_es[pos] = g_src[e];
}

// ---------------- layer-1 aggregation: warp per node, F=256 ----------------
__global__ void agg1_k(const float* __restrict__ x) {
    int node = (blockIdx.x * blockDim.x + threadIdx.x) >> 5;
    if (node >= NN) return;
    const int lane = threadIdx.x & 31;

    const float disd = g_dis[node];
    const float4* xs = (const float4*)&x[(size_t)node * IN_DIM];
    float4 a0 = xs[lane], a1 = xs[lane + 32];
    const float self = disd * disd;
    a0.x *= self; a0.y *= self; a0.z *= self; a0.w *= self;
    a1.x *= self; a1.y *= self; a1.z *= self; a1.w *= self;

    const int beg = g_rowptr[node], end = g_rowptr[node + 1];
    for (int j = beg; j < end; j++) {
        int s = g_es[j];
        float nrm = g_dis[s] * disd;
        const float4* hs = (const float4*)&x[(size_t)s * IN_DIM];
        float4 v0 = hs[lane], v1 = hs[lane + 32];
        a0.x += v0.x * nrm; a0.y += v0.y * nrm; a0.z += v0.z * nrm; a0.w += v0.w * nrm;
        a1.x += v1.x * nrm; a1.y += v1.y * nrm; a1.z += v1.z * nrm; a1.w += v1.w * nrm;
    }
    float4* o = (float4*)&g_aggx[(size_t)node * IN_DIM];
    o[lane] = a0;
    o[lane + 32] = a1;
}

// ---------------- TF32 WMMA GEMM ----------------
// LAYER 1: A = g_aggx [NN_PAD x 256], B = W1 [256 x 512], OUT = g_feat1
//          with FUSED epilogue (bias + PReLU + dropout), rows >= NN skipped.
// LAYER 2: A = g_feat1 [NN_PAD x 512], B = W2 [512 x 128], OUT = g_h2 (plain)
template <int LAYER>
__global__ void __launch_bounds__(256, 2) wgemm_k(const float* __restrict__ B,
                                                  const float* __restrict__ bias,
                                                  const void* __restrict__ mask_raw,
                                                  const float* __restrict__ a_ptr) {
    constexpr int K  = (LAYER == 1) ? IN_DIM : H1;
    constexpr int Nc = (LAYER == 1) ? H1 : H2;
    const float* __restrict__ A = (LAYER == 1) ? g_aggx : g_feat1;
    float* __restrict__ C       = (LAYER == 1) ? g_feat1 : g_h2;

    constexpr int BM = 128, BN = 128, BK = 16;
    constexpr int NIT = K / BK;
    constexpr int LDA = BK + 4;
    constexpr int LDB = BN + 4;

    __shared__ float As[2][BM][LDA];
    __shared__ float Bs[2][BK][LDB];

    const int t = threadIdx.x;
    const int warp = t >> 5;
    const int lane = t & 31;
    const int wr = warp >> 2;
    const int wc = warp & 3;
    const size_t block_row = (size_t)blockIdx.y * BM;
    const int    block_col = blockIdx.x * BN;

    const int a_r = t >> 1, a_c = (t & 1) << 3;
    const int b_r = t >> 4, b_c = (t & 15) << 3;

    float4 ra0, ra1, rb0, rb1;
    {
        const float* ap = &A[(block_row + a_r) * K + a_c];
        ra0 = *(const float4*)ap; ra1 = *(const float4*)(ap + 4);
        const float* bp = &B[(size_t)b_r * Nc + block_col + b_c];
        rb0 = *(const float4*)bp; rb1 = *(const float4*)(bp + 4);
    }
    *(float4*)&As[0][a_r][a_c]     = ra0;
    *(float4*)&As[0][a_r][a_c + 4] = ra1;
    *(float4*)&Bs[0][b_r][b_c]     = rb0;
    *(float4*)&Bs[0][b_r][b_c + 4] = rb1;
    __syncthreads();

    wmma::fragment<wmma::accumulator, 16, 16, 8, float> acc[4][2];
#pragma unroll
    for (int i = 0; i < 4; i++)
#pragma unroll
        for (int j = 0; j < 2; j++) wmma::fill_fragment(acc[i][j], 0.0f);

    for (int it = 0; it < NIT; it++) {
        const int buf = it & 1;
        const bool has_next = (it + 1 < NIT);
        if (has_next) {
            const int k0 = (it + 1) * BK;
            const float* ap = &A[(block_row + a_r) * K + k0 + a_c];
            ra0 = *(const float4*)ap; ra1 = *(const float4*)(ap + 4);
            const float* bp = &B[(size_t)(k0 + b_r) * Nc + block_col + b_c];
            rb0 = *(const float4*)bp; rb1 = *(const float4*)(bp + 4);
        }

#pragma unroll
        for (int ks = 0; ks < 2; ks++) {
            wmma::fragment<wmma::matrix_a, 16, 16, 8, wmma::precision::tf32, wmma::row_major> fa[4];
            wmma::fragment<wmma::matrix_b, 16, 16, 8, wmma::precision::tf32, wmma::row_major> fb[2];
#pragma unroll
            for (int i = 0; i < 4; i++) {
                wmma::load_matrix_sync(fa[i], &As[buf][wr * 64 + i * 16][ks * 8], LDA);
#pragma unroll
                for (int e = 0; e < fa[i].num_elements; e++)
                    fa[i].x[e] = wmma::__float_to_tf32(fa[i].x[e]);
            }
#pragma unroll
            for (int j = 0; j < 2; j++) {
                wmma::load_matrix_sync(fb[j], &Bs[buf][ks * 8][wc * 32 + j * 16], LDB);
#pragma unroll
                for (int e = 0; e < fb[j].num_elements; e++)
                    fb[j].x[e] = wmma::__float_to_tf32(fb[j].x[e]);
            }
#pragma unroll
            for (int i = 0; i < 4; i++)
#pragma unroll
                for (int j = 0; j < 2; j++)
                    wmma::mma_sync(acc[i][j], fa[i], fb[j], acc[i][j]);
        }

        __syncthreads();
        if (has_next) {
            const int nb = buf ^ 1;
            *(float4*)&As[nb][a_r][a_c]     = ra0;
            *(float4*)&As[nb][a_r][a_c + 4] = ra1;
            *(float4*)&Bs[nb][b_r][b_c]     = rb0;
            *(float4*)&Bs[nb][b_r][b_c + 4] = rb1;
            __syncthreads();
        }
    }

    if (LAYER == 2) {
        // plain store (C padded -> no guards)
#pragma unroll
        for (int i = 0; i < 4; i++)
#pragma unroll
            for (int j = 0; j < 2; j++) {
                float* cp = &C[(block_row + wr * 64 + i * 16) * Nc
                               + block_col + wc * 32 + j * 16];
                wmma::store_matrix_sync(cp, acc[i][j], Nc, wmma::mem_row_major);
            }
    } else {
        // fused epilogue: stage each 16x16 fragment in smem (ldm=20, a
        // multiple of 4 as WMMA requires for fp32), apply bias + PReLU +
        // dropout, write to g_feat1. Rows >= NN skipped (stay .bss-zero;
        // wgemm2 depends on that).
        __syncthreads();  // done reading As/Bs; reuse As as staging
        constexpr int SLD = 20;                       // stage leading dim
        float* stage = ((float*)As) + warp * (16 * SLD);  // 320 floats/warp
        const float aval = __ldg(a_ptr);
        const int mk = g_mask_kind;
        const int r = lane >> 1;            // 0..15
        const int cq = (lane & 1) << 3;     // 0 or 8

#pragma unroll
        for (int i = 0; i < 4; i++)
#pragma unroll
            for (int j = 0; j < 2; j++) {
                wmma::store_matrix_sync(stage, acc[i][j], SLD, wmma::mem_row_major);
                __syncwarp();
                size_t row = block_row + wr * 64 + i * 16 + r;
                if (row < NN) {
                    int col = block_col + wc * 32 + j * 16 + cq;
                    const size_t oidx = row * Nc + col;
                    float v[8];
#pragma unroll
                    for (int q = 0; q < 8; q++) {
                        float u = stage[r * SLD + cq + q] + bias[col + q];
                        u = (u >= 0.0f) ? u : aval * u;
                        bool keep;
                        if (mk == 1)      keep = ((const float*)mask_raw)[oidx + q] != 0.0f;
                        else if (mk == 2) keep = ((const int*)mask_raw)[oidx + q] != 0;
                        else if (mk == 3) keep = ((const long long*)mask_raw)[oidx + q] != 0;
                        else              keep = ((const unsigned char*)mask_raw)[oidx + q] != 0;
                        v[q] = keep ? u * 2.0f : 0.0f;
                    }
                    *(float4*)&C[oidx]     = make_float4(v[0], v[1], v[2], v[3]);
                    *(float4*)&C[oidx + 4] = make_float4(v[4], v[5], v[6], v[7]);
                }
                __syncwarp();
            }
    }
}

// ---------------- layer-2 aggregation FUSED with epilogue 2 ------------------
__global__ void agg2_fused_k(const float* __restrict__ bias,
                             const void* __restrict__ mask_raw,
                             const float* __restrict__ a_ptr,
                             float* __restrict__ out) {
    int node = (blockIdx.x * blockDim.x + threadIdx.x) >> 5;
    if (node >= NN) return;
    const int lane = threadIdx.x & 31;

    const float disd = g_dis[node];
    const float4* hs = (const float4*)&g_h2[(size_t)node * H2];
    float4 acc = hs[lane];
    const float self = disd * disd;
    acc.x *= self; acc.y *= self; acc.z *= self; acc.w *= self;

    const int beg = g_rowptr[node], end = g_rowptr[node + 1];
    for (int j = beg; j < end; j++) {
        int s = g_es[j];
        float nrm = g_dis[s] * disd;
        const float4* vs = (const float4*)&g_h2[(size_t)s * H2];
        float4 v = vs[lane];
        acc.x += v.x * nrm; acc.y += v.y * nrm; acc.z += v.z * nrm; acc.w += v.w * nrm;
    }

    const float4 b = *(const float4*)&bias[lane * 4];
    const float a = __ldg(a_ptr);
    acc.x += b.x; acc.y += b.y; acc.z += b.z; acc.w += b.w;
    acc.x = (acc.x >= 0.0f) ? acc.x : a * acc.x;
    acc.y = (acc.y >= 0.0f) ? acc.y : a * acc.y;
    acc.z = (acc.z >= 0.0f) ? acc.z : a * acc.z;
    acc.w = (acc.w >= 0.0f) ? acc.w : a * acc.w;

    const size_t mi = (size_t)node * H2 + lane * 4;
    bool k0, k1, k2, k3;
    int mk = g_mask_kind;
    if (mk == 1) {
        float4 m = *(const float4*)&((const float*)mask_raw)[mi];
        k0 = m.x != 0.0f; k1 = m.y != 0.0f; k2 = m.z != 0.0f; k3 = m.w != 0.0f;
    } else if (mk == 2) {
        int4 m = *(const int4*)&((const int*)mask_raw)[mi];
        k0 = m.x != 0; k1 = m.y != 0; k2 = m.z != 0; k3 = m.w != 0;
    } else if (mk == 3) {
        const long long* m = &((const long long*)mask_raw)[mi];
        k0 = m[0] != 0; k1 = m[1] != 0; k2 = m[2] != 0; k3 = m[3] != 0;
    } else {
        uchar4 m = *(const uchar4*)&((const unsigned char*)mask_raw)[mi];
        k0 = m.x != 0; k1 = m.y != 0; k2 = m.z != 0; k3 = m.w != 0;
    }
    acc.x = k0 ? acc.x * 2.0f : 0.0f;
    acc.y = k1 ? acc.y * 2.0f : 0.0f;
    acc.z = k2 ? acc.z * 2.0f : 0.0f;
    acc.w = k3 ? acc.w * 2.0f : 0.0f;

    *(float4*)&out[(size_t)node * H2 + lane * 4] = acc;
}

// ---------------- launch (kernel launches only; graph-capturable) -----------
extern "C" void kernel_launch(void* const* d_in, const int* in_sizes, int n_in,
                              void* d_out, int out_size) {
    const float* x      = (const float*)d_in[0];
    const void*  ei_raw = d_in[1];
    const float* W1     = (const float*)d_in[2];
    const float* b1     = (const float*)d_in[3];
    const float* W2     = (const float*)d_in[4];
    const float* b2     = (const float*)d_in[5];
    const float* a      = (const float*)d_in[6];
    const void*  m1     = d_in[7];
    const void*  m2     = d_in[8];
    float* out          = (float*)d_out;

    const int T = 256;

    // launch order tuned so ncu (-s 5) lands on wgemm_k<1>:
    // 0: prep, 1: hist, 2: scan, 3: scatter, 4: agg1, 5: wgemm1, 6: wgemm2, 7: agg2
    prep_k<<<(EE + T - 1) / T, T>>>(ei_raw, m1);
    hist_k<<<(EE + T - 1) / T, T>>>();
    scan_k<<<1, 1024>>>();
    scatter_k<<<(EE + T - 1) / T, T>>>();

    agg1_k<<<(NN * 32 + T - 1) / T, T>>>(x);
    {
        dim3 grid(H1 / 128, NN_PAD / 128);
        wgemm_k<1><<<grid, 256>>>(W1, b1, m1, a);   // fused epilogue -> g_feat1
    }
    {
        dim3 grid(H2 / 128, NN_PAD / 128);
        wgemm_k<2><<<grid, 256>>>(W2, nullptr, nullptr, nullptr);
    }
    agg2_fused_k<<<(NN * 32 + T - 1) / T, T>>>(b2, m2, a, out);
}